// round 10
// baseline (speedup 1.0000x reference)
#include <cuda_runtime.h>
#include <cuda_bf16.h>
#include <cstdint>

// out[i, s] = sigmoid( sqrt(sum_j X[i,j]^2 * exp(lv[j])) * z[s] + sum_j X[i,j]*mu[j] )
// N = 500000 rows, D = 64, NS = 128.
//
// FINAL (R5, converged): non-persistent, half-warp per row, 4 rows/warp.
//   - lane loads float4 of its row: one LDG.128 warp-instr = 2 full rows (512B)
//   - butterfly reduce over 16 lanes (offsets 8,4,2,1), 4 chains interleaved
//   - sigmoid(a) = 0.5*tanh(a/2)+0.5 via MUFU.TANH (1 MUFU/elem)
//   - __ldcs on X (read-once) / __stcs on out (write-once)
//   - 0.5 folded into per-lane z constants (one fewer mul per row)
//   - 32 regs -> 8 CTA/SM, ~77% occupancy
// Measured: 61.0 us wall / 55.6 us ncu, DRAM 73.8% — at the mixed-stream
// (1:2 R:W) HBM ceiling; five structural variants all pinned at 72-74% DRAM.

__device__ __forceinline__ float fast_tanh(float a) {
    float t;
    asm("tanh.approx.f32 %0, %1;" : "=f"(t) : "f"(a));
    return t;
}

__device__ __forceinline__ float fast_sqrt(float v) {
    float s;
    asm("sqrt.approx.f32 %0, %1;" : "=f"(s) : "f"(v));
    return s;
}

__device__ __forceinline__ void dot_pair(const float4& x, const float4& mu,
                                         const float4& ew, float& m, float& v) {
    m = x.x * mu.x;
    m = fmaf(x.y, mu.y, m);
    m = fmaf(x.z, mu.z, m);
    m = fmaf(x.w, mu.w, m);
    v = (x.x * x.x) * ew.x;
    v = fmaf(x.y * x.y, ew.y, v);
    v = fmaf(x.z * x.z, ew.z, v);
    v = fmaf(x.w * x.w, ew.w, v);
}

// zA/zB already pre-scaled by 0.5. a/2 = sqrt(v)*(0.5 z) + 0.5 m
__device__ __forceinline__ void emit_row(float m, float v,
                                         const float4& zA, const float4& zB,
                                         float* __restrict__ orow, int hl) {
    const float s  = fast_sqrt(v);
    const float mh = 0.5f * m;
    float4 ra, rb;
    ra.x = fmaf(fast_tanh(fmaf(s, zA.x, mh)), 0.5f, 0.5f);
    ra.y = fmaf(fast_tanh(fmaf(s, zA.y, mh)), 0.5f, 0.5f);
    ra.z = fmaf(fast_tanh(fmaf(s, zA.z, mh)), 0.5f, 0.5f);
    ra.w = fmaf(fast_tanh(fmaf(s, zA.w, mh)), 0.5f, 0.5f);
    rb.x = fmaf(fast_tanh(fmaf(s, zB.x, mh)), 0.5f, 0.5f);
    rb.y = fmaf(fast_tanh(fmaf(s, zB.y, mh)), 0.5f, 0.5f);
    rb.z = fmaf(fast_tanh(fmaf(s, zB.z, mh)), 0.5f, 0.5f);
    rb.w = fmaf(fast_tanh(fmaf(s, zB.w, mh)), 0.5f, 0.5f);
    __stcs(reinterpret_cast<float4*>(orow) + hl, ra);
    __stcs(reinterpret_cast<float4*>(orow) + hl + 16, rb);
}

__global__ __launch_bounds__(256) void blr_sigmoid_kernel(
    const float* __restrict__ X,
    const float* __restrict__ w_mu,
    const float* __restrict__ w_lv,
    const float* __restrict__ z,
    float* __restrict__ out,
    int n)
{
    const int lane = threadIdx.x & 31;
    const int hl   = lane & 15;          // position within half-warp
    const int half = lane >> 4;          // 0 or 1: which row of the pair
    const int warp_global = (blockIdx.x * blockDim.x + threadIdx.x) >> 5;

    // Per-lane constants
    const float4 mu4 = reinterpret_cast<const float4*>(w_mu)[hl];
    const float4 lv4 = reinterpret_cast<const float4*>(w_lv)[hl];
    const float4 ew4 = make_float4(__expf(lv4.x), __expf(lv4.y),
                                   __expf(lv4.z), __expf(lv4.w));
    float4 zA = reinterpret_cast<const float4*>(z)[hl];
    float4 zB = reinterpret_cast<const float4*>(z)[hl + 16];
    zA.x *= 0.5f; zA.y *= 0.5f; zA.z *= 0.5f; zA.w *= 0.5f;
    zB.x *= 0.5f; zB.y *= 0.5f; zB.z *= 0.5f; zB.w *= 0.5f;

    // This warp owns rows [base, base+3]; this lane's rows: base+half, base+2+half
    const int base = warp_global * 4;
    const int r0 = base + half;
    const int r1 = base + 2 + half;
    if (r0 >= n) return;
    const bool have1 = (r1 < n);

    // Hoist both loads (MLP=2), streaming policy
    float4 x0 = __ldcs(reinterpret_cast<const float4*>(X + (size_t)r0 * 64) + hl);
    float4 x1 = make_float4(0.f, 0.f, 0.f, 0.f);
    if (have1) x1 = __ldcs(reinterpret_cast<const float4*>(X + (size_t)r1 * 64) + hl);

    float m0, v0, m1, v1;
    dot_pair(x0, mu4, ew4, m0, v0);
    dot_pair(x1, mu4, ew4, m1, v1);

    // Butterfly over the 16-lane group; 4 chains interleaved for ILP
    #pragma unroll
    for (int o = 8; o > 0; o >>= 1) {
        m0 += __shfl_xor_sync(0xffffffffu, m0, o);
        v0 += __shfl_xor_sync(0xffffffffu, v0, o);
        m1 += __shfl_xor_sync(0xffffffffu, m1, o);
        v1 += __shfl_xor_sync(0xffffffffu, v1, o);
    }

    emit_row(m0, v0, zA, zB, out + (size_t)r0 * 128, hl);
    if (have1) emit_row(m1, v1, zA, zB, out + (size_t)r1 * 128, hl);
}

extern "C" void kernel_launch(void* const* d_in, const int* in_sizes, int n_in,
                              void* d_out, int out_size) {
    const float* X    = (const float*)d_in[0];
    const float* w_mu = (const float*)d_in[1];
    const float* w_lv = (const float*)d_in[2];
    const float* z    = (const float*)d_in[3];
    float* out = (float*)d_out;

    const int n = in_sizes[0] / 64;                  // 500000 rows
    const int rows_per_block = 4 * (256 / 32);       // 4 rows/warp * 8 warps
    const int blocks = (n + rows_per_block - 1) / rows_per_block;

    blr_sigmoid_kernel<<<blocks, 256>>>(X, w_mu, w_lv, z, out, n);
}

// round 11
// speedup vs baseline: 1.0411x; 1.0411x over previous
#include <cuda_runtime.h>
#include <cuda_bf16.h>
#include <cstdint>

// out[i, s] = sigmoid( sqrt(sum_j X[i,j]^2 * exp(lv[j])) * z[s] + sum_j X[i,j]*mu[j] )
// N = 500000 rows, D = 64, NS = 128.
//
// FINAL (R5, converged): non-persistent, half-warp per row, 4 rows/warp.
//   - lane loads float4 of its row: one LDG.128 warp-instr = 2 full rows (512B)
//   - butterfly reduce over 16 lanes (offsets 8,4,2,1), 4 chains interleaved
//   - sigmoid(a) = 0.5*tanh(a/2)+0.5 via MUFU.TANH (1 MUFU/elem)
//   - __ldcs on X (read-once) / __stcs on out (write-once)
//   - 0.5 folded into per-lane z constants (one fewer mul per row)
//   - 32 regs -> 8 CTA/SM, ~77-81% occupancy
// Best measured: 61.0 us wall / 55.6 us ncu, DRAM 73.8% (good-clock run).
// R10 re-run of this exact binary: 64.0 us with HBM at 5051 GB/s — DVFS noise,
// not kernel. Five structural variants all pinned at 72-74% DRAM on nominal
// clocks: mixed-stream (1:2 R:W) HBM ceiling; 384 MB traffic is irreducible.

__device__ __forceinline__ float fast_tanh(float a) {
    float t;
    asm("tanh.approx.f32 %0, %1;" : "=f"(t) : "f"(a));
    return t;
}

__device__ __forceinline__ float fast_sqrt(float v) {
    float s;
    asm("sqrt.approx.f32 %0, %1;" : "=f"(s) : "f"(v));
    return s;
}

__device__ __forceinline__ void dot_pair(const float4& x, const float4& mu,
                                         const float4& ew, float& m, float& v) {
    m = x.x * mu.x;
    m = fmaf(x.y, mu.y, m);
    m = fmaf(x.z, mu.z, m);
    m = fmaf(x.w, mu.w, m);
    v = (x.x * x.x) * ew.x;
    v = fmaf(x.y * x.y, ew.y, v);
    v = fmaf(x.z * x.z, ew.z, v);
    v = fmaf(x.w * x.w, ew.w, v);
}

// zA/zB already pre-scaled by 0.5. a/2 = sqrt(v)*(0.5 z) + 0.5 m
__device__ __forceinline__ void emit_row(float m, float v,
                                         const float4& zA, const float4& zB,
                                         float* __restrict__ orow, int hl) {
    const float s  = fast_sqrt(v);
    const float mh = 0.5f * m;
    float4 ra, rb;
    ra.x = fmaf(fast_tanh(fmaf(s, zA.x, mh)), 0.5f, 0.5f);
    ra.y = fmaf(fast_tanh(fmaf(s, zA.y, mh)), 0.5f, 0.5f);
    ra.z = fmaf(fast_tanh(fmaf(s, zA.z, mh)), 0.5f, 0.5f);
    ra.w = fmaf(fast_tanh(fmaf(s, zA.w, mh)), 0.5f, 0.5f);
    rb.x = fmaf(fast_tanh(fmaf(s, zB.x, mh)), 0.5f, 0.5f);
    rb.y = fmaf(fast_tanh(fmaf(s, zB.y, mh)), 0.5f, 0.5f);
    rb.z = fmaf(fast_tanh(fmaf(s, zB.z, mh)), 0.5f, 0.5f);
    rb.w = fmaf(fast_tanh(fmaf(s, zB.w, mh)), 0.5f, 0.5f);
    __stcs(reinterpret_cast<float4*>(orow) + hl, ra);
    __stcs(reinterpret_cast<float4*>(orow) + hl + 16, rb);
}

__global__ __launch_bounds__(256) void blr_sigmoid_kernel(
    const float* __restrict__ X,
    const float* __restrict__ w_mu,
    const float* __restrict__ w_lv,
    const float* __restrict__ z,
    float* __restrict__ out,
    int n)
{
    const int lane = threadIdx.x & 31;
    const int hl   = lane & 15;          // position within half-warp
    const int half = lane >> 4;          // 0 or 1: which row of the pair
    const int warp_global = (blockIdx.x * blockDim.x + threadIdx.x) >> 5;

    // Per-lane constants
    const float4 mu4 = reinterpret_cast<const float4*>(w_mu)[hl];
    const float4 lv4 = reinterpret_cast<const float4*>(w_lv)[hl];
    const float4 ew4 = make_float4(__expf(lv4.x), __expf(lv4.y),
                                   __expf(lv4.z), __expf(lv4.w));
    float4 zA = reinterpret_cast<const float4*>(z)[hl];
    float4 zB = reinterpret_cast<const float4*>(z)[hl + 16];
    zA.x *= 0.5f; zA.y *= 0.5f; zA.z *= 0.5f; zA.w *= 0.5f;
    zB.x *= 0.5f; zB.y *= 0.5f; zB.z *= 0.5f; zB.w *= 0.5f;

    // This warp owns rows [base, base+3]; this lane's rows: base+half, base+2+half
    const int base = warp_global * 4;
    const int r0 = base + half;
    const int r1 = base + 2 + half;
    if (r0 >= n) return;
    const bool have1 = (r1 < n);

    // Hoist both loads (MLP=2), streaming policy
    float4 x0 = __ldcs(reinterpret_cast<const float4*>(X + (size_t)r0 * 64) + hl);
    float4 x1 = make_float4(0.f, 0.f, 0.f, 0.f);
    if (have1) x1 = __ldcs(reinterpret_cast<const float4*>(X + (size_t)r1 * 64) + hl);

    float m0, v0, m1, v1;
    dot_pair(x0, mu4, ew4, m0, v0);
    dot_pair(x1, mu4, ew4, m1, v1);

    // Butterfly over the 16-lane group; 4 chains interleaved for ILP
    #pragma unroll
    for (int o = 8; o > 0; o >>= 1) {
        m0 += __shfl_xor_sync(0xffffffffu, m0, o);
        v0 += __shfl_xor_sync(0xffffffffu, v0, o);
        m1 += __shfl_xor_sync(0xffffffffu, m1, o);
        v1 += __shfl_xor_sync(0xffffffffu, v1, o);
    }

    emit_row(m0, v0, zA, zB, out + (size_t)r0 * 128, hl);
    if (have1) emit_row(m1, v1, zA, zB, out + (size_t)r1 * 128, hl);
}

extern "C" void kernel_launch(void* const* d_in, const int* in_sizes, int n_in,
                              void* d_out, int out_size) {
    const float* X    = (const float*)d_in[0];
    const float* w_mu = (const float*)d_in[1];
    const float* w_lv = (const float*)d_in[2];
    const float* z    = (const float*)d_in[3];
    float* out = (float*)d_out;

    const int n = in_sizes[0] / 64;                  // 500000 rows
    const int rows_per_block = 4 * (256 / 32);       // 4 rows/warp * 8 warps
    const int blocks = (n + rows_per_block - 1) / rows_per_block;

    blr_sigmoid_kernel<<<blocks, 256>>>(X, w_mu, w_lv, z, out, n);
}

// round 13
// speedup vs baseline: 1.0422x; 1.0010x over previous
#include <cuda_runtime.h>
#include <cuda_bf16.h>
#include <cstdint>

// out[i, s] = sigmoid( sqrt(sum_j X[i,j]^2 * exp(lv[j])) * z[s] + sum_j X[i,j]*mu[j] )
// N = 500000 rows, D = 64, NS = 128.
//
// FINAL (converged): non-persistent, half-warp per row, 4 rows/warp.
//   - lane loads float4 of its row: one LDG.128 warp-instr = 2 full rows (512B)
//   - butterfly reduce over 16 lanes (offsets 8,4,2,1), 4 chains interleaved
//   - sigmoid(a) = 0.5*tanh(a/2)+0.5 via MUFU.TANH (1 MUFU/elem)
//   - __ldcs on X (read-once) / __stcs on out (write-once)
//   - 0.5 folded into per-lane z constants (one fewer mul per row)
//   - 32 regs -> 8 CTA/SM, ~78% occupancy
//
// Convergence evidence (7 rounds):
//   this shape: 61.0 / 61.5 / 61.5 us wall (ncu 55.6-56.9), DRAM 72-74%
//   persistent loop:    67.9 us (occ 53%)     - worse
//   cp.async pipeline:  67.6 us (occ 59%)     - worse
//   8 rows/warp MLP=4:  61.5 us (occ 58%)     - neutral
//   DRAM% invariant at 72-74% across occ 53-81% and 3 load mechanisms:
//   mixed-stream (1:2 R:W) HBM ceiling; 384 MB traffic is irreducible.

__device__ __forceinline__ float fast_tanh(float a) {
    float t;
    asm("tanh.approx.f32 %0, %1;" : "=f"(t) : "f"(a));
    return t;
}

__device__ __forceinline__ float fast_sqrt(float v) {
    float s;
    asm("sqrt.approx.f32 %0, %1;" : "=f"(s) : "f"(v));
    return s;
}

__device__ __forceinline__ void dot_pair(const float4& x, const float4& mu,
                                         const float4& ew, float& m, float& v) {
    m = x.x * mu.x;
    m = fmaf(x.y, mu.y, m);
    m = fmaf(x.z, mu.z, m);
    m = fmaf(x.w, mu.w, m);
    v = (x.x * x.x) * ew.x;
    v = fmaf(x.y * x.y, ew.y, v);
    v = fmaf(x.z * x.z, ew.z, v);
    v = fmaf(x.w * x.w, ew.w, v);
}

// zA/zB already pre-scaled by 0.5. a/2 = sqrt(v)*(0.5 z) + 0.5 m
__device__ __forceinline__ void emit_row(float m, float v,
                                         const float4& zA, const float4& zB,
                                         float* __restrict__ orow, int hl) {
    const float s  = fast_sqrt(v);
    const float mh = 0.5f * m;
    float4 ra, rb;
    ra.x = fmaf(fast_tanh(fmaf(s, zA.x, mh)), 0.5f, 0.5f);
    ra.y = fmaf(fast_tanh(fmaf(s, zA.y, mh)), 0.5f, 0.5f);
    ra.z = fmaf(fast_tanh(fmaf(s, zA.z, mh)), 0.5f, 0.5f);
    ra.w = fmaf(fast_tanh(fmaf(s, zA.w, mh)), 0.5f, 0.5f);
    rb.x = fmaf(fast_tanh(fmaf(s, zB.x, mh)), 0.5f, 0.5f);
    rb.y = fmaf(fast_tanh(fmaf(s, zB.y, mh)), 0.5f, 0.5f);
    rb.z = fmaf(fast_tanh(fmaf(s, zB.z, mh)), 0.5f, 0.5f);
    rb.w = fmaf(fast_tanh(fmaf(s, zB.w, mh)), 0.5f, 0.5f);
    __stcs(reinterpret_cast<float4*>(orow) + hl, ra);
    __stcs(reinterpret_cast<float4*>(orow) + hl + 16, rb);
}

__global__ __launch_bounds__(256) void blr_sigmoid_kernel(
    const float* __restrict__ X,
    const float* __restrict__ w_mu,
    const float* __restrict__ w_lv,
    const float* __restrict__ z,
    float* __restrict__ out,
    int n)
{
    const int lane = threadIdx.x & 31;
    const int hl   = lane & 15;          // position within half-warp
    const int half = lane >> 4;          // 0 or 1: which row of the pair
    const int warp_global = (blockIdx.x * blockDim.x + threadIdx.x) >> 5;

    // Per-lane constants
    const float4 mu4 = reinterpret_cast<const float4*>(w_mu)[hl];
    const float4 lv4 = reinterpret_cast<const float4*>(w_lv)[hl];
    const float4 ew4 = make_float4(__expf(lv4.x), __expf(lv4.y),
                                   __expf(lv4.z), __expf(lv4.w));
    float4 zA = reinterpret_cast<const float4*>(z)[hl];
    float4 zB = reinterpret_cast<const float4*>(z)[hl + 16];
    zA.x *= 0.5f; zA.y *= 0.5f; zA.z *= 0.5f; zA.w *= 0.5f;
    zB.x *= 0.5f; zB.y *= 0.5f; zB.z *= 0.5f; zB.w *= 0.5f;

    // This warp owns rows [base, base+3]; this lane's rows: base+half, base+2+half
    const int base = warp_global * 4;
    const int r0 = base + half;
    const int r1 = base + 2 + half;
    if (r0 >= n) return;
    const bool have1 = (r1 < n);

    // Hoist both loads (MLP=2), streaming policy
    float4 x0 = __ldcs(reinterpret_cast<const float4*>(X + (size_t)r0 * 64) + hl);
    float4 x1 = make_float4(0.f, 0.f, 0.f, 0.f);
    if (have1) x1 = __ldcs(reinterpret_cast<const float4*>(X + (size_t)r1 * 64) + hl);

    float m0, v0, m1, v1;
    dot_pair(x0, mu4, ew4, m0, v0);
    dot_pair(x1, mu4, ew4, m1, v1);

    // Butterfly over the 16-lane group; 4 chains interleaved for ILP
    #pragma unroll
    for (int o = 8; o > 0; o >>= 1) {
        m0 += __shfl_xor_sync(0xffffffffu, m0, o);
        v0 += __shfl_xor_sync(0xffffffffu, v0, o);
        m1 += __shfl_xor_sync(0xffffffffu, m1, o);
        v1 += __shfl_xor_sync(0xffffffffu, v1, o);
    }

    emit_row(m0, v0, zA, zB, out + (size_t)r0 * 128, hl);
    if (have1) emit_row(m1, v1, zA, zB, out + (size_t)r1 * 128, hl);
}

extern "C" void kernel_launch(void* const* d_in, const int* in_sizes, int n_in,
                              void* d_out, int out_size) {
    const float* X    = (const float*)d_in[0];
    const float* w_mu = (const float*)d_in[1];
    const float* w_lv = (const float*)d_in[2];
    const float* z    = (const float*)d_in[3];
    float* out = (float*)d_out;

    const int n = in_sizes[0] / 64;                  // 500000 rows
    const int rows_per_block = 4 * (256 / 32);       // 4 rows/warp * 8 warps
    const int blocks = (n + rows_per_block - 1) / rows_per_block;

    blr_sigmoid_kernel<<<blocks, 256>>>(X, w_mu, w_lv, z, out, n);
}

// round 14
// speedup vs baseline: 1.0476x; 1.0052x over previous
#include <cuda_runtime.h>
#include <cuda_bf16.h>
#include <cstdint>

// out[i, s] = sigmoid( sqrt(sum_j X[i,j]^2 * exp(lv[j])) * z[s] + sum_j X[i,j]*mu[j] )
// N = 500000 rows, D = 64, NS = 128.
//
// FINAL (converged): non-persistent, half-warp per row, 4 rows/warp.
//   - lane loads float4 of its row: one LDG.128 warp-instr = 2 full rows (512B)
//   - butterfly reduce over 16 lanes (offsets 8,4,2,1), 4 chains interleaved
//   - sigmoid(a) = 0.5*tanh(a/2)+0.5 via MUFU.TANH (1 MUFU/elem)
//   - __ldcs on X (read-once) / __stcs on out (write-once)
//   - 0.5 folded into per-lane z constants (one fewer mul per row)
//   - 32 regs -> 8 CTA/SM, ~76-81% occupancy
//
// Convergence evidence (8 rounds):
//   this shape: 61.0 / 61.5 / 61.5 / 61.4 us wall (ncu 55.6-56.9), DRAM 72-74%
//   persistent loop:    67.9 us - worse;  cp.async pipeline: 67.6 us - worse
//   8 rows/warp MLP=4:  61.5 us - neutral
//   DRAM% invariant at 72-74% across occ 53-81% and 3 load mechanisms:
//   mixed-stream (1:2 R:W) HBM ceiling; 384 MB logical traffic is irreducible
//   (measured ~325 MB in-kernel: tail of write stream drains from L2 after exit).

__device__ __forceinline__ float fast_tanh(float a) {
    float t;
    asm("tanh.approx.f32 %0, %1;" : "=f"(t) : "f"(a));
    return t;
}

__device__ __forceinline__ float fast_sqrt(float v) {
    float s;
    asm("sqrt.approx.f32 %0, %1;" : "=f"(s) : "f"(v));
    return s;
}

__device__ __forceinline__ void dot_pair(const float4& x, const float4& mu,
                                         const float4& ew, float& m, float& v) {
    m = x.x * mu.x;
    m = fmaf(x.y, mu.y, m);
    m = fmaf(x.z, mu.z, m);
    m = fmaf(x.w, mu.w, m);
    v = (x.x * x.x) * ew.x;
    v = fmaf(x.y * x.y, ew.y, v);
    v = fmaf(x.z * x.z, ew.z, v);
    v = fmaf(x.w * x.w, ew.w, v);
}

// zA/zB already pre-scaled by 0.5. a/2 = sqrt(v)*(0.5 z) + 0.5 m
__device__ __forceinline__ void emit_row(float m, float v,
                                         const float4& zA, const float4& zB,
                                         float* __restrict__ orow, int hl) {
    const float s  = fast_sqrt(v);
    const float mh = 0.5f * m;
    float4 ra, rb;
    ra.x = fmaf(fast_tanh(fmaf(s, zA.x, mh)), 0.5f, 0.5f);
    ra.y = fmaf(fast_tanh(fmaf(s, zA.y, mh)), 0.5f, 0.5f);
    ra.z = fmaf(fast_tanh(fmaf(s, zA.z, mh)), 0.5f, 0.5f);
    ra.w = fmaf(fast_tanh(fmaf(s, zA.w, mh)), 0.5f, 0.5f);
    rb.x = fmaf(fast_tanh(fmaf(s, zB.x, mh)), 0.5f, 0.5f);
    rb.y = fmaf(fast_tanh(fmaf(s, zB.y, mh)), 0.5f, 0.5f);
    rb.z = fmaf(fast_tanh(fmaf(s, zB.z, mh)), 0.5f, 0.5f);
    rb.w = fmaf(fast_tanh(fmaf(s, zB.w, mh)), 0.5f, 0.5f);
    __stcs(reinterpret_cast<float4*>(orow) + hl, ra);
    __stcs(reinterpret_cast<float4*>(orow) + hl + 16, rb);
}

__global__ __launch_bounds__(256) void blr_sigmoid_kernel(
    const float* __restrict__ X,
    const float* __restrict__ w_mu,
    const float* __restrict__ w_lv,
    const float* __restrict__ z,
    float* __restrict__ out,
    int n)
{
    const int lane = threadIdx.x & 31;
    const int hl   = lane & 15;          // position within half-warp
    const int half = lane >> 4;          // 0 or 1: which row of the pair
    const int warp_global = (blockIdx.x * blockDim.x + threadIdx.x) >> 5;

    // Per-lane constants
    const float4 mu4 = reinterpret_cast<const float4*>(w_mu)[hl];
    const float4 lv4 = reinterpret_cast<const float4*>(w_lv)[hl];
    const float4 ew4 = make_float4(__expf(lv4.x), __expf(lv4.y),
                                   __expf(lv4.z), __expf(lv4.w));
    float4 zA = reinterpret_cast<const float4*>(z)[hl];
    float4 zB = reinterpret_cast<const float4*>(z)[hl + 16];
    zA.x *= 0.5f; zA.y *= 0.5f; zA.z *= 0.5f; zA.w *= 0.5f;
    zB.x *= 0.5f; zB.y *= 0.5f; zB.z *= 0.5f; zB.w *= 0.5f;

    // This warp owns rows [base, base+3]; this lane's rows: base+half, base+2+half
    const int base = warp_global * 4;
    const int r0 = base + half;
    const int r1 = base + 2 + half;
    if (r0 >= n) return;
    const bool have1 = (r1 < n);

    // Hoist both loads (MLP=2), streaming policy
    float4 x0 = __ldcs(reinterpret_cast<const float4*>(X + (size_t)r0 * 64) + hl);
    float4 x1 = make_float4(0.f, 0.f, 0.f, 0.f);
    if (have1) x1 = __ldcs(reinterpret_cast<const float4*>(X + (size_t)r1 * 64) + hl);

    float m0, v0, m1, v1;
    dot_pair(x0, mu4, ew4, m0, v0);
    dot_pair(x1, mu4, ew4, m1, v1);

    // Butterfly over the 16-lane group; 4 chains interleaved for ILP
    #pragma unroll
    for (int o = 8; o > 0; o >>= 1) {
        m0 += __shfl_xor_sync(0xffffffffu, m0, o);
        v0 += __shfl_xor_sync(0xffffffffu, v0, o);
        m1 += __shfl_xor_sync(0xffffffffu, m1, o);
        v1 += __shfl_xor_sync(0xffffffffu, v1, o);
    }

    emit_row(m0, v0, zA, zB, out + (size_t)r0 * 128, hl);
    if (have1) emit_row(m1, v1, zA, zB, out + (size_t)r1 * 128, hl);
}

extern "C" void kernel_launch(void* const* d_in, const int* in_sizes, int n_in,
                              void* d_out, int out_size) {
    const float* X    = (const float*)d_in[0];
    const float* w_mu = (const float*)d_in[1];
    const float* w_lv = (const float*)d_in[2];
    const float* z    = (const float*)d_in[3];
    float* out = (float*)d_out;

    const int n = in_sizes[0] / 64;                  // 500000 rows
    const int rows_per_block = 4 * (256 / 32);       // 4 rows/warp * 8 warps
    const int blocks = (n + rows_per_block - 1) / rows_per_block;

    blr_sigmoid_kernel<<<blocks, 256>>>(X, w_mu, w_lv, z, out, n);
}

// round 16
// speedup vs baseline: 1.0695x; 1.0208x over previous
#include <cuda_runtime.h>
#include <cuda_bf16.h>
#include <cstdint>

// out[i, s] = sigmoid( sqrt(sum_j X[i,j]^2 * exp(lv[j])) * z[s] + sum_j X[i,j]*mu[j] )
// N = 500000 rows, D = 64, NS = 128.
//
// FINAL (converged): non-persistent, half-warp per row, 4 rows/warp.
//   - lane loads float4 of its row: one LDG.128 warp-instr = 2 full rows (512B)
//   - butterfly reduce over 16 lanes (offsets 8,4,2,1), 4 chains interleaved
//   - sigmoid(a) = 0.5*tanh(a/2)+0.5 via MUFU.TANH (1 MUFU/elem)
//   - __ldcs on X (read-once) / __stcs on out (write-once)
//   - 0.5 folded into per-lane z constants (one fewer mul per row)
//   - 32 regs -> 8 CTA/SM, ~76-81% occupancy
//
// Convergence evidence (9 rounds):
//   this shape: 61.0 / 61.5 / 61.5 / 61.4 / 61.1 us wall (ncu 55.6-56.9),
//   DRAM 72-74%; one bad-DVFS outlier at 64.0 us (HBM 5051 GB/s).
//   persistent loop: 67.9 us - worse;  cp.async pipeline: 67.6 us - worse;
//   8 rows/warp MLP=4: 61.5 us - neutral (register/occupancy trade).
//   DRAM% invariant at 72-74% across occ 53-81% and 3 load mechanisms:
//   mixed-stream (1:2 R:W) HBM ceiling; 384 MB logical traffic is irreducible
//   (measured ~325 MB in-kernel: tail of write stream drains from L2 after exit).

__device__ __forceinline__ float fast_tanh(float a) {
    float t;
    asm("tanh.approx.f32 %0, %1;" : "=f"(t) : "f"(a));
    return t;
}

__device__ __forceinline__ float fast_sqrt(float v) {
    float s;
    asm("sqrt.approx.f32 %0, %1;" : "=f"(s) : "f"(v));
    return s;
}

__device__ __forceinline__ void dot_pair(const float4& x, const float4& mu,
                                         const float4& ew, float& m, float& v) {
    m = x.x * mu.x;
    m = fmaf(x.y, mu.y, m);
    m = fmaf(x.z, mu.z, m);
    m = fmaf(x.w, mu.w, m);
    v = (x.x * x.x) * ew.x;
    v = fmaf(x.y * x.y, ew.y, v);
    v = fmaf(x.z * x.z, ew.z, v);
    v = fmaf(x.w * x.w, ew.w, v);
}

// zA/zB already pre-scaled by 0.5. a/2 = sqrt(v)*(0.5 z) + 0.5 m
__device__ __forceinline__ void emit_row(float m, float v,
                                         const float4& zA, const float4& zB,
                                         float* __restrict__ orow, int hl) {
    const float s  = fast_sqrt(v);
    const float mh = 0.5f * m;
    float4 ra, rb;
    ra.x = fmaf(fast_tanh(fmaf(s, zA.x, mh)), 0.5f, 0.5f);
    ra.y = fmaf(fast_tanh(fmaf(s, zA.y, mh)), 0.5f, 0.5f);
    ra.z = fmaf(fast_tanh(fmaf(s, zA.z, mh)), 0.5f, 0.5f);
    ra.w = fmaf(fast_tanh(fmaf(s, zA.w, mh)), 0.5f, 0.5f);
    rb.x = fmaf(fast_tanh(fmaf(s, zB.x, mh)), 0.5f, 0.5f);
    rb.y = fmaf(fast_tanh(fmaf(s, zB.y, mh)), 0.5f, 0.5f);
    rb.z = fmaf(fast_tanh(fmaf(s, zB.z, mh)), 0.5f, 0.5f);
    rb.w = fmaf(fast_tanh(fmaf(s, zB.w, mh)), 0.5f, 0.5f);
    __stcs(reinterpret_cast<float4*>(orow) + hl, ra);
    __stcs(reinterpret_cast<float4*>(orow) + hl + 16, rb);
}

__global__ __launch_bounds__(256) void blr_sigmoid_kernel(
    const float* __restrict__ X,
    const float* __restrict__ w_mu,
    const float* __restrict__ w_lv,
    const float* __restrict__ z,
    float* __restrict__ out,
    int n)
{
    const int lane = threadIdx.x & 31;
    const int hl   = lane & 15;          // position within half-warp
    const int half = lane >> 4;          // 0 or 1: which row of the pair
    const int warp_global = (blockIdx.x * blockDim.x + threadIdx.x) >> 5;

    // Per-lane constants
    const float4 mu4 = reinterpret_cast<const float4*>(w_mu)[hl];
    const float4 lv4 = reinterpret_cast<const float4*>(w_lv)[hl];
    const float4 ew4 = make_float4(__expf(lv4.x), __expf(lv4.y),
                                   __expf(lv4.z), __expf(lv4.w));
    float4 zA = reinterpret_cast<const float4*>(z)[hl];
    float4 zB = reinterpret_cast<const float4*>(z)[hl + 16];
    zA.x *= 0.5f; zA.y *= 0.5f; zA.z *= 0.5f; zA.w *= 0.5f;
    zB.x *= 0.5f; zB.y *= 0.5f; zB.z *= 0.5f; zB.w *= 0.5f;

    // This warp owns rows [base, base+3]; this lane's rows: base+half, base+2+half
    const int base = warp_global * 4;
    const int r0 = base + half;
    const int r1 = base + 2 + half;
    if (r0 >= n) return;
    const bool have1 = (r1 < n);

    // Hoist both loads (MLP=2), streaming policy
    float4 x0 = __ldcs(reinterpret_cast<const float4*>(X + (size_t)r0 * 64) + hl);
    float4 x1 = make_float4(0.f, 0.f, 0.f, 0.f);
    if (have1) x1 = __ldcs(reinterpret_cast<const float4*>(X + (size_t)r1 * 64) + hl);

    float m0, v0, m1, v1;
    dot_pair(x0, mu4, ew4, m0, v0);
    dot_pair(x1, mu4, ew4, m1, v1);

    // Butterfly over the 16-lane group; 4 chains interleaved for ILP
    #pragma unroll
    for (int o = 8; o > 0; o >>= 1) {
        m0 += __shfl_xor_sync(0xffffffffu, m0, o);
        v0 += __shfl_xor_sync(0xffffffffu, v0, o);
        m1 += __shfl_xor_sync(0xffffffffu, m1, o);
        v1 += __shfl_xor_sync(0xffffffffu, v1, o);
    }

    emit_row(m0, v0, zA, zB, out + (size_t)r0 * 128, hl);
    if (have1) emit_row(m1, v1, zA, zB, out + (size_t)r1 * 128, hl);
}

extern "C" void kernel_launch(void* const* d_in, const int* in_sizes, int n_in,
                              void* d_out, int out_size) {
    const float* X    = (const float*)d_in[0];
    const float* w_mu = (const float*)d_in[1];
    const float* w_lv = (const float*)d_in[2];
    const float* z    = (const float*)d_in[3];
    float* out = (float*)d_out;

    const int n = in_sizes[0] / 64;                  // 500000 rows
    const int rows_per_block = 4 * (256 / 32);       // 4 rows/warp * 8 warps
    const int blocks = (n + rows_per_block - 1) / rows_per_block;

    blr_sigmoid_kernel<<<blocks, 256>>>(X, w_mu, w_lv, z, out, n);
}